// round 3
// baseline (speedup 1.0000x reference)
#include <cuda_runtime.h>
#include <math.h>

#define N_NODES 50000
#define N_EDGES 800000
#define HID 128
#define F_NODE 128
#define F_EDGE 32
#define HEADS 8
#define F_OUT 16
#define SLOPE 0.2f
#define LN_EPS 1e-5f

// ---------------- scratch (no allocations allowed) ----------------
__device__ __align__(16) float g_hn[(size_t)N_NODES * HID];          // node linear output
__device__ __align__(16) float g_stgt[N_NODES * HEADS];              // a[0:16] . hn[n,h,:]
__device__ __align__(16) float g_ssrc[N_NODES * HEADS];              // a[16:32]. hn[n,h,:]
__device__ __align__(16) float g_logits[(size_t)N_EDGES * HEADS];    // leakyrelu logits
__device__ __align__(16) float g_logits_s[(size_t)N_EDGES * HEADS];  // CSR-sorted logits
__device__ int   g_src_s[N_EDGES];                     // CSR-sorted src ids
__device__ int   g_cnt[N_NODES];
__device__ int   g_off[N_NODES + 1];
__device__ int   g_cursor[N_NODES];

// ---------------- K0: zero histogram ----------------
__global__ void k_zero() {
    int i = blockIdx.x * 256 + threadIdx.x;
    if (i < N_NODES) g_cnt[i] = 0;
}

// ---------------- K1: node GEMM hn = nf @ W^T + b ----------------
// 128 threads (thread = output channel o), 16 nodes per block.
__global__ void __launch_bounds__(128) k_node_gemm(const float* __restrict__ nf,
                                                   const float* __restrict__ W,
                                                   const float* __restrict__ b) {
    __shared__ __align__(16) float Ws[32 * 129];  // [kk][o], padded
    __shared__ __align__(16) float nfs[16 * 32];  // [n][k]
    const int tid = threadIdx.x;
    const int n0 = blockIdx.x * 16;
    float acc[16];
#pragma unroll
    for (int i = 0; i < 16; i++) acc[i] = 0.f;

    for (int k0 = 0; k0 < 128; k0 += 32) {
        __syncthreads();
#pragma unroll
        for (int j = 0; j < 32; j++) {
            int idx = tid + j * 128;         // idx = o*32 + kk
            int o = idx >> 5, kk = idx & 31;
            Ws[kk * 129 + o] = W[o * 128 + k0 + kk];
        }
#pragma unroll
        for (int j = 0; j < 4; j++) {
            int idx = tid + j * 128;         // idx = n*32 + k
            int n = idx >> 5, k = idx & 31;
            nfs[n * 32 + k] = nf[(size_t)(n0 + n) * 128 + k0 + k];
        }
        __syncthreads();
#pragma unroll
        for (int kq = 0; kq < 8; kq++) {
            float w0 = Ws[(kq * 4 + 0) * 129 + tid];
            float w1 = Ws[(kq * 4 + 1) * 129 + tid];
            float w2 = Ws[(kq * 4 + 2) * 129 + tid];
            float w3 = Ws[(kq * 4 + 3) * 129 + tid];
#pragma unroll
            for (int n = 0; n < 16; n++) {
                float4 x = *(const float4*)&nfs[n * 32 + kq * 4];
                acc[n] += x.x * w0 + x.y * w1 + x.z * w2 + x.w * w3;
            }
        }
    }
    float bb = b[tid];
#pragma unroll
    for (int n = 0; n < 16; n++)
        g_hn[(size_t)(n0 + n) * 128 + tid] = acc[n] + bb;
}

// ---------------- K1b: per-node attention scalars ----------------
// 256 threads = 2 nodes; 128 threads per node, thread = channel.
__global__ void k_scores(const float* __restrict__ aw) {
    int tid = threadIdx.x;
    int n = blockIdx.x * 2 + (tid >> 7);
    int c = tid & 127;
    float v = g_hn[(size_t)n * 128 + c];
    int f = c & 15;
    float s1 = v * aw[f];
    float s2 = v * aw[16 + f];
#pragma unroll
    for (int m = 8; m; m >>= 1) {
        s1 += __shfl_xor_sync(0xffffffffu, s1, m);
        s2 += __shfl_xor_sync(0xffffffffu, s2, m);
    }
    if (f == 0) {
        g_stgt[n * 8 + (c >> 4)] = s1;
        g_ssrc[n * 8 + (c >> 4)] = s2;
    }
}

// ---------------- K2: edge GEMM + LN(edge_out) + logits + histogram ----------------
// warp-per-edge; each lane owns 4 consecutive output channels; We rows live in
// registers (4 x 32 floats). ef tile staged in smem (broadcast reads per warp).
__global__ void __launch_bounds__(128) k_edge(const float* __restrict__ ef,
                                              const int* __restrict__ ei,
                                              const float* __restrict__ We,
                                              const float* __restrict__ be,
                                              const float* __restrict__ aw,
                                              const float* __restrict__ ab,
                                              const float* __restrict__ gamma,
                                              const float* __restrict__ beta,
                                              float* __restrict__ edge_out) {
    __shared__ __align__(16) float efs[128 * 32];  // 128 edges x 32 feats
    const int tid = threadIdx.x;
    const int lane = tid & 31;
    const int warp = tid >> 5;
    const int c0 = lane * 4;
    const int h = c0 >> 4;

    float w0r[32], w1r[32], w2r[32], w3r[32];
#pragma unroll
    for (int k = 0; k < 32; k++) {
        w0r[k] = We[(c0 + 0) * 32 + k];
        w1r[k] = We[(c0 + 1) * 32 + k];
        w2r[k] = We[(c0 + 2) * 32 + k];
        w3r[k] = We[(c0 + 3) * 32 + k];
    }
    const float be0 = be[c0], be1 = be[c0 + 1], be2 = be[c0 + 2], be3 = be[c0 + 3];
    const float gm0 = gamma[c0], gm1 = gamma[c0 + 1], gm2 = gamma[c0 + 2], gm3 = gamma[c0 + 3];
    const float bt0 = beta[c0], bt1 = beta[c0 + 1], bt2 = beta[c0 + 2], bt3 = beta[c0 + 3];
    const int f0 = c0 & 15;
    const float af0 = aw[32 + f0], af1 = aw[32 + f0 + 1], af2 = aw[32 + f0 + 2],
                af3 = aw[32 + f0 + 3];
    const float abv = ab[0];

    const int NTILES = N_EDGES / 128;
    for (int tile = blockIdx.x; tile < NTILES; tile += gridDim.x) {
        __syncthreads();
        const int ebase = tile * 128;
#pragma unroll
        for (int j = 0; j < 8; j++) {
            int idx = tid + j * 128;
            *(float4*)&efs[idx * 4] = *(const float4*)&ef[(size_t)ebase * 32 + idx * 4];
        }
        __syncthreads();

        for (int i = 0; i < 32; i++) {
            const int el = warp * 32 + i;
            const int e = ebase + el;
            float v0 = 0.f, v1 = 0.f, v2 = 0.f, v3 = 0.f;
#pragma unroll
            for (int k = 0; k < 32; k++) {
                float x = efs[el * 32 + k];   // warp-uniform -> smem broadcast
                v0 += x * w0r[k];
                v1 += x * w1r[k];
                v2 += x * w2r[k];
                v3 += x * w3r[k];
            }
            v0 += be0; v1 += be1; v2 += be2; v3 += be3;

            // s_e: per-head reduction (4 lanes per head)
            float p = v0 * af0 + v1 * af1 + v2 * af2 + v3 * af3;
            p += __shfl_xor_sync(0xffffffffu, p, 1);
            p += __shfl_xor_sync(0xffffffffu, p, 2);

            // LayerNorm stats over all 128 channels (warp-wide)
            float s1 = v0 + v1 + v2 + v3;
            float s2 = v0 * v0 + v1 * v1 + v2 * v2 + v3 * v3;
#pragma unroll
            for (int m = 16; m; m >>= 1) {
                s1 += __shfl_xor_sync(0xffffffffu, s1, m);
                s2 += __shfl_xor_sync(0xffffffffu, s2, m);
            }
            float mu = s1 * (1.f / 128.f);
            float var = s2 * (1.f / 128.f) - mu * mu;
            float rs = rsqrtf(var + LN_EPS);

            float4 o;
            o.x = (v0 - mu) * rs * gm0 + bt0;
            o.y = (v1 - mu) * rs * gm1 + bt1;
            o.z = (v2 - mu) * rs * gm2 + bt2;
            o.w = (v3 - mu) * rs * gm3 + bt3;
            *(float4*)&edge_out[(size_t)e * 128 + c0] = o;

            if ((lane & 3) == 0) {
                int src = ei[e];
                int tgt = ei[N_EDGES + e];
                float lg = g_stgt[tgt * 8 + h] + g_ssrc[src * 8 + h] + p + abv;
                lg = lg > 0.f ? lg : SLOPE * lg;
                g_logits[(size_t)e * 8 + h] = lg;
                if (h == 0) atomicAdd(&g_cnt[tgt], 1);
            }
        }
    }
}

// ---------------- K3: single-block exclusive scan ----------------
__global__ void __launch_bounds__(1024) k_scan() {
    __shared__ int ps[1024];
    const int tid = threadIdx.x;
    const int CH = (N_NODES + 1023) / 1024;  // 49
    int s0 = tid * CH;
    int s1 = s0 + CH; if (s1 > N_NODES) s1 = N_NODES;
    int s = 0;
    for (int i = s0; i < s1; i++) s += g_cnt[i];
    ps[tid] = s;
    __syncthreads();
    for (int d = 1; d < 1024; d <<= 1) {
        int v = ps[tid];
        int add = (tid >= d) ? ps[tid - d] : 0;
        __syncthreads();
        ps[tid] = v + add;
        __syncthreads();
    }
    int run = ps[tid] - s;  // exclusive prefix
    for (int i = s0; i < s1; i++) {
        g_off[i] = run;
        g_cursor[i] = run;
        run += g_cnt[i];
    }
    if (tid == 1023) g_off[N_NODES] = ps[1023];
}

// ---------------- K4: scatter edges into CSR order ----------------
__global__ void k_scatter(const int* __restrict__ ei) {
    int e = blockIdx.x * 256 + threadIdx.x;
    if (e >= N_EDGES) return;
    int tgt = ei[N_EDGES + e];
    int pos = atomicAdd(&g_cursor[tgt], 1);
    g_src_s[pos] = ei[e];
    const float4* s = (const float4*)&g_logits[(size_t)e * 8];
    float4* d = (float4*)&g_logits_s[(size_t)pos * 8];
    d[0] = s[0];
    d[1] = s[1];
}

// ---------------- K5: per-node softmax + aggregate + LN + ELU ----------------
__global__ void __launch_bounds__(128) k_node_out(const float* __restrict__ gamma,
                                                  const float* __restrict__ beta,
                                                  float* __restrict__ out) {
    __shared__ float sm[8], si[8];
    __shared__ float r1[4], r2[4];
    const int n = blockIdx.x;
    const int tid = threadIdx.x;
    const int off = g_off[n];
    const int deg = g_off[n + 1] - off;

    if (tid < 32) {
        int hh = tid >> 2, j = tid & 3;
        float m = -3.0e38f;
        for (int d = j; d < deg; d += 4)
            m = fmaxf(m, g_logits_s[(size_t)(off + d) * 8 + hh]);
        m = fmaxf(m, __shfl_xor_sync(0xffffffffu, m, 1));
        m = fmaxf(m, __shfl_xor_sync(0xffffffffu, m, 2));
        float s = 0.f;
        for (int d = j; d < deg; d += 4)
            s += __expf(g_logits_s[(size_t)(off + d) * 8 + hh] - m);
        s += __shfl_xor_sync(0xffffffffu, s, 1);
        s += __shfl_xor_sync(0xffffffffu, s, 2);
        if (j == 0) {
            sm[hh] = m;
            si[hh] = s > 0.f ? 1.f / s : 0.f;
        }
    }
    __syncthreads();

    const int c = tid;
    const int h = c >> 4;
    const float mh = sm[h];
    const float ih = si[h];
    float acc = 0.f;
    for (int d = 0; d < deg; d++) {
        float lg = g_logits_s[(size_t)(off + d) * 8 + h];
        int src = g_src_s[off + d];
        acc += __expf(lg - mh) * ih * g_hn[(size_t)src * 128 + c];
    }
    acc += (float)deg * g_hn[(size_t)n * 128 + c];

    float s1 = acc, s2 = acc * acc;
#pragma unroll
    for (int m = 16; m; m >>= 1) {
        s1 += __shfl_xor_sync(0xffffffffu, s1, m);
        s2 += __shfl_xor_sync(0xffffffffu, s2, m);
    }
    if ((tid & 31) == 0) {
        r1[tid >> 5] = s1;
        r2[tid >> 5] = s2;
    }
    __syncthreads();
    float S1 = r1[0] + r1[1] + r1[2] + r1[3];
    float S2 = r2[0] + r2[1] + r2[2] + r2[3];
    float mu = S1 * (1.f / 128.f);
    float var = S2 * (1.f / 128.f) - mu * mu;
    float rs = rsqrtf(var + LN_EPS);
    float y = (acc - mu) * rs * gamma[c] + beta[c];
    out[(size_t)n * 128 + c] = y > 0.f ? y : expm1f(y);
}

// ---------------- launcher ----------------
extern "C" void kernel_launch(void* const* d_in, const int* in_sizes, int n_in,
                              void* d_out, int out_size) {
    const float* nf = (const float*)d_in[0];
    const float* ef = (const float*)d_in[1];
    const int* ei = (const int*)d_in[2];
    const float* W = (const float*)d_in[3];
    const float* b = (const float*)d_in[4];
    const float* We = (const float*)d_in[5];
    const float* be = (const float*)d_in[6];
    const float* aw = (const float*)d_in[7];
    const float* ab = (const float*)d_in[8];
    const float* gamma = (const float*)d_in[9];
    const float* beta = (const float*)d_in[10];

    float* out_nodes = (float*)d_out;
    float* out_edges = out_nodes + (size_t)N_NODES * HID;

    k_zero<<<(N_NODES + 255) / 256, 256>>>();
    k_node_gemm<<<N_NODES / 16, 128>>>(nf, W, b);
    k_scores<<<N_NODES / 2, 256>>>(aw);
    k_edge<<<592, 128>>>(ef, ei, We, be, aw, ab, gamma, beta, out_edges);
    k_scan<<<1, 1024>>>();
    k_scatter<<<(N_EDGES + 255) / 256, 256>>>(ei);
    k_node_out<<<N_NODES, 128>>>(gamma, beta, out_nodes);
}

// round 6
// speedup vs baseline: 1.0672x; 1.0672x over previous
#include <cuda_runtime.h>
#include <math.h>

#define N_NODES 50000
#define N_EDGES 800000
#define HID 128
#define F_NODE 128
#define F_EDGE 32
#define HEADS 8
#define F_OUT 16
#define SLOPE 0.2f
#define LN_EPS 1e-5f

// ---------------- scratch (no allocations allowed) ----------------
__device__ __align__(16) float g_hn[(size_t)N_NODES * HID];          // node linear output
__device__ __align__(16) float g_stgt[N_NODES * HEADS];              // a[0:16] . hn[n,h,:]
__device__ __align__(16) float g_ssrc[N_NODES * HEADS];              // a[16:32]. hn[n,h,:]
__device__ __align__(16) float g_logits[(size_t)N_EDGES * HEADS];    // leakyrelu logits
__device__ __align__(16) float g_logits_s[(size_t)N_EDGES * HEADS];  // CSR-sorted logits
__device__ int   g_src_s[N_EDGES];                     // CSR-sorted src ids
__device__ int   g_cnt[N_NODES];
__device__ int   g_off[N_NODES + 1];
__device__ int   g_cursor[N_NODES];

// ---------------- K0: zero histogram ----------------
__global__ void k_zero() {
    int i = blockIdx.x * 256 + threadIdx.x;
    if (i < N_NODES) g_cnt[i] = 0;
}

// ---------------- K1: node GEMM hn = nf @ W^T + b ----------------
__global__ void __launch_bounds__(128) k_node_gemm(const float* __restrict__ nf,
                                                   const float* __restrict__ W,
                                                   const float* __restrict__ b) {
    __shared__ __align__(16) float Ws[32 * 129];  // [kk][o], padded
    __shared__ __align__(16) float nfs[16 * 32];  // [n][k]
    const int tid = threadIdx.x;
    const int n0 = blockIdx.x * 16;
    float acc[16];
#pragma unroll
    for (int i = 0; i < 16; i++) acc[i] = 0.f;

    for (int k0 = 0; k0 < 128; k0 += 32) {
        __syncthreads();
#pragma unroll
        for (int j = 0; j < 32; j++) {
            int idx = tid + j * 128;         // idx = o*32 + kk
            int o = idx >> 5, kk = idx & 31;
            Ws[kk * 129 + o] = W[o * 128 + k0 + kk];
        }
#pragma unroll
        for (int j = 0; j < 4; j++) {
            int idx = tid + j * 128;         // idx = n*32 + k
            int n = idx >> 5, k = idx & 31;
            nfs[n * 32 + k] = nf[(size_t)(n0 + n) * 128 + k0 + k];
        }
        __syncthreads();
#pragma unroll
        for (int kq = 0; kq < 8; kq++) {
            float w0 = Ws[(kq * 4 + 0) * 129 + tid];
            float w1 = Ws[(kq * 4 + 1) * 129 + tid];
            float w2 = Ws[(kq * 4 + 2) * 129 + tid];
            float w3 = Ws[(kq * 4 + 3) * 129 + tid];
#pragma unroll
            for (int n = 0; n < 16; n++) {
                float4 x = *(const float4*)&nfs[n * 32 + kq * 4];
                acc[n] += x.x * w0 + x.y * w1 + x.z * w2 + x.w * w3;
            }
        }
    }
    float bb = b[tid];
#pragma unroll
    for (int n = 0; n < 16; n++)
        g_hn[(size_t)(n0 + n) * 128 + tid] = acc[n] + bb;
}

// ---------------- K1b: per-node attention scalars ----------------
__global__ void k_scores(const float* __restrict__ aw) {
    int tid = threadIdx.x;
    int n = blockIdx.x * 2 + (tid >> 7);
    int c = tid & 127;
    float v = g_hn[(size_t)n * 128 + c];
    int f = c & 15;
    float s1 = v * aw[f];
    float s2 = v * aw[16 + f];
#pragma unroll
    for (int m = 8; m; m >>= 1) {
        s1 += __shfl_xor_sync(0xffffffffu, s1, m);
        s2 += __shfl_xor_sync(0xffffffffu, s2, m);
    }
    if (f == 0) {
        g_stgt[n * 8 + (c >> 4)] = s1;
        g_ssrc[n * 8 + (c >> 4)] = s2;
    }
}

// ---------------- K2 v2: edge GEMM + LN + logits + histogram ----------------
// 256 threads. Weights in SMEM [k][c] (one LDS.128/k/lane, amortized over 8
// edges). Each warp accumulates 8 edges at a time (32 FMA : 9 LDS per k).
__global__ void __launch_bounds__(256) k_edge(const float* __restrict__ ef,
                                              const int* __restrict__ ei,
                                              const float* __restrict__ We,
                                              const float* __restrict__ be,
                                              const float* __restrict__ aw,
                                              const float* __restrict__ ab,
                                              const float* __restrict__ gamma,
                                              const float* __restrict__ beta,
                                              float* __restrict__ edge_out) {
    __shared__ __align__(16) float Wsm[32 * 128];  // [k][c]
    __shared__ __align__(16) float efs[128 * 32];  // [e][k]
    const int tid = threadIdx.x;
    const int lane = tid & 31;
    const int warp = tid >> 5;
    const int c0 = lane * 4;
    const int h = c0 >> 4;

    // stage transposed weights once per block (L2-hot after first block)
    for (int i = tid; i < 32 * 128; i += 256) {
        int k = i >> 7, c = i & 127;
        Wsm[i] = We[c * 32 + k];
    }

    const float be0 = be[c0], be1 = be[c0 + 1], be2 = be[c0 + 2], be3 = be[c0 + 3];
    const float gm0 = gamma[c0], gm1 = gamma[c0 + 1], gm2 = gamma[c0 + 2], gm3 = gamma[c0 + 3];
    const float bt0 = beta[c0], bt1 = beta[c0 + 1], bt2 = beta[c0 + 2], bt3 = beta[c0 + 3];
    const int f0 = c0 & 15;
    const float af0 = aw[32 + f0], af1 = aw[32 + f0 + 1], af2 = aw[32 + f0 + 2],
                af3 = aw[32 + f0 + 3];
    const float abv = ab[0];

    const int NTILES = N_EDGES / 128;
    for (int tile = blockIdx.x; tile < NTILES; tile += gridDim.x) {
        __syncthreads();
        const int ebase = tile * 128;
        // stage 128 edges x 32 feats: 4096 floats, 16 per thread (coalesced)
#pragma unroll
        for (int j = 0; j < 4; j++) {
            int idx = tid + j * 256;
            *(float4*)&efs[idx * 4] = *(const float4*)&ef[(size_t)ebase * 32 + idx * 4];
        }
        __syncthreads();

#pragma unroll
        for (int g = 0; g < 2; g++) {
            const int e0 = warp * 16 + g * 8;
            float4 acc[8];
#pragma unroll
            for (int e = 0; e < 8; e++) acc[e] = make_float4(0.f, 0.f, 0.f, 0.f);

#pragma unroll
            for (int k = 0; k < 32; k++) {
                float4 w = *(const float4*)&Wsm[k * 128 + c0];
#pragma unroll
                for (int e = 0; e < 8; e++) {
                    float x = efs[(e0 + e) * 32 + k];  // warp-uniform broadcast
                    acc[e].x += x * w.x;
                    acc[e].y += x * w.y;
                    acc[e].z += x * w.z;
                    acc[e].w += x * w.w;
                }
            }

#pragma unroll
            for (int e = 0; e < 8; e++) {
                float v0 = acc[e].x + be0, v1 = acc[e].y + be1;
                float v2 = acc[e].z + be2, v3 = acc[e].w + be3;

                // s_e: per-head reduction (4 lanes per head)
                float p = v0 * af0 + v1 * af1 + v2 * af2 + v3 * af3;
                p += __shfl_xor_sync(0xffffffffu, p, 1);
                p += __shfl_xor_sync(0xffffffffu, p, 2);

                // LayerNorm stats over 128 channels (warp-wide)
                float s1 = v0 + v1 + v2 + v3;
                float s2 = v0 * v0 + v1 * v1 + v2 * v2 + v3 * v3;
#pragma unroll
                for (int m = 16; m; m >>= 1) {
                    s1 += __shfl_xor_sync(0xffffffffu, s1, m);
                    s2 += __shfl_xor_sync(0xffffffffu, s2, m);
                }
                float mu = s1 * (1.f / 128.f);
                float var = s2 * (1.f / 128.f) - mu * mu;
                float rs = rsqrtf(var + LN_EPS);

                const int eg = ebase + e0 + e;
                float4 o;
                o.x = (v0 - mu) * rs * gm0 + bt0;
                o.y = (v1 - mu) * rs * gm1 + bt1;
                o.z = (v2 - mu) * rs * gm2 + bt2;
                o.w = (v3 - mu) * rs * gm3 + bt3;
                *(float4*)&edge_out[(size_t)eg * 128 + c0] = o;

                if ((lane & 3) == 0) {
                    int src = ei[eg];
                    int tgt = ei[N_EDGES + eg];
                    float lg = g_stgt[tgt * 8 + h] + g_ssrc[src * 8 + h] + p + abv;
                    lg = lg > 0.f ? lg : SLOPE * lg;
                    g_logits[(size_t)eg * 8 + h] = lg;
                    if (h == 0) atomicAdd(&g_cnt[tgt], 1);
                }
            }
        }
    }
}

// ---------------- K3: single-block exclusive scan ----------------
__global__ void __launch_bounds__(1024) k_scan() {
    __shared__ int ps[1024];
    const int tid = threadIdx.x;
    const int CH = (N_NODES + 1023) / 1024;  // 49
    int s0 = tid * CH;
    int s1 = s0 + CH; if (s1 > N_NODES) s1 = N_NODES;
    int s = 0;
    for (int i = s0; i < s1; i++) s += g_cnt[i];
    ps[tid] = s;
    __syncthreads();
    for (int d = 1; d < 1024; d <<= 1) {
        int v = ps[tid];
        int add = (tid >= d) ? ps[tid - d] : 0;
        __syncthreads();
        ps[tid] = v + add;
        __syncthreads();
    }
    int run = ps[tid] - s;  // exclusive prefix
    for (int i = s0; i < s1; i++) {
        g_off[i] = run;
        g_cursor[i] = run;
        run += g_cnt[i];
    }
    if (tid == 1023) g_off[N_NODES] = ps[1023];
}

// ---------------- K4: scatter edges into CSR order ----------------
__global__ void k_scatter(const int* __restrict__ ei) {
    int e = blockIdx.x * 256 + threadIdx.x;
    if (e >= N_EDGES) return;
    int tgt = ei[N_EDGES + e];
    int pos = atomicAdd(&g_cursor[tgt], 1);
    g_src_s[pos] = ei[e];
    const float4* s = (const float4*)&g_logits[(size_t)e * 8];
    float4* d = (float4*)&g_logits_s[(size_t)pos * 8];
    d[0] = s[0];
    d[1] = s[1];
}

// ---------------- K5 v2: softmax + aggregate + LN + ELU ----------------
// Stages src ids + alpha in smem per 128-edge chunk, unrolls gather for MLP.
__global__ void __launch_bounds__(128) k_node_out(const float* __restrict__ gamma,
                                                  const float* __restrict__ beta,
                                                  float* __restrict__ out) {
    __shared__ float sm[8], si[8];
    __shared__ float r1[4], r2[4];
    __shared__ int ssrc[128];
    __shared__ float salpha[128 * 8];
    const int n = blockIdx.x;
    const int tid = threadIdx.x;
    const int off = g_off[n];
    const int deg = g_off[n + 1] - off;

    if (tid < 32) {
        int hh = tid >> 2, j = tid & 3;
        float m = -3.0e38f;
        for (int d = j; d < deg; d += 4)
            m = fmaxf(m, g_logits_s[(size_t)(off + d) * 8 + hh]);
        m = fmaxf(m, __shfl_xor_sync(0xffffffffu, m, 1));
        m = fmaxf(m, __shfl_xor_sync(0xffffffffu, m, 2));
        float s = 0.f;
        for (int d = j; d < deg; d += 4)
            s += __expf(g_logits_s[(size_t)(off + d) * 8 + hh] - m);
        s += __shfl_xor_sync(0xffffffffu, s, 1);
        s += __shfl_xor_sync(0xffffffffu, s, 2);
        if (j == 0) {
            sm[hh] = m;
            si[hh] = s > 0.f ? 1.f / s : 0.f;
        }
    }
    __syncthreads();

    const int c = tid;
    const int h = c >> 4;
    float acc = 0.f;
    for (int base = 0; base < deg; base += 128) {
        const int m = min(128, deg - base);
        __syncthreads();
        if (tid < m) ssrc[tid] = g_src_s[off + base + tid];
        for (int i = tid; i < m * 8; i += 128) {
            int hh = i & 7;
            salpha[i] = __expf(g_logits_s[(size_t)(off + base) * 8 + i] - sm[hh]) * si[hh];
        }
        __syncthreads();
#pragma unroll 4
        for (int d = 0; d < m; d++)
            acc += salpha[d * 8 + h] * g_hn[(size_t)ssrc[d] * 128 + c];
    }
    acc += (float)deg * g_hn[(size_t)n * 128 + c];

    float s1 = acc, s2 = acc * acc;
#pragma unroll
    for (int m = 16; m; m >>= 1) {
        s1 += __shfl_xor_sync(0xffffffffu, s1, m);
        s2 += __shfl_xor_sync(0xffffffffu, s2, m);
    }
    if ((tid & 31) == 0) {
        r1[tid >> 5] = s1;
        r2[tid >> 5] = s2;
    }
    __syncthreads();
    float S1 = r1[0] + r1[1] + r1[2] + r1[3];
    float S2 = r2[0] + r2[1] + r2[2] + r2[3];
    float mu = S1 * (1.f / 128.f);
    float var = S2 * (1.f / 128.f) - mu * mu;
    float rs = rsqrtf(var + LN_EPS);
    float y = (acc - mu) * rs * gamma[c] + beta[c];
    out[(size_t)n * 128 + c] = y > 0.f ? y : expm1f(y);
}

// ---------------- launcher ----------------
extern "C" void kernel_launch(void* const* d_in, const int* in_sizes, int n_in,
                              void* d_out, int out_size) {
    const float* nf = (const float*)d_in[0];
    const float* ef = (const float*)d_in[1];
    const int* ei = (const int*)d_in[2];
    const float* W = (const float*)d_in[3];
    const float* b = (const float*)d_in[4];
    const float* We = (const float*)d_in[5];
    const float* be = (const float*)d_in[6];
    const float* aw = (const float*)d_in[7];
    const float* ab = (const float*)d_in[8];
    const float* gamma = (const float*)d_in[9];
    const float* beta = (const float*)d_in[10];

    float* out_nodes = (float*)d_out;
    float* out_edges = out_nodes + (size_t)N_NODES * HID;

    k_zero<<<(N_NODES + 255) / 256, 256>>>();
    k_node_gemm<<<N_NODES / 16, 128>>>(nf, W, b);
    k_scores<<<N_NODES / 2, 256>>>(aw);
    k_edge<<<444, 256>>>(ef, ei, We, be, aw, ab, gamma, beta, out_edges);
    k_scan<<<1, 1024>>>();
    k_scatter<<<(N_EDGES + 255) / 256, 256>>>(ei);
    k_node_out<<<N_NODES, 128>>>(gamma, beta, out_nodes);
}